// round 2
// baseline (speedup 1.0000x reference)
#include <cuda_runtime.h>
#include <cstdint>
#include <cstddef>

// ---------------------------------------------------------------------------
// Problem dims
// ---------------------------------------------------------------------------
#define LQ 281
#define BQ 256
#define VQ 512
#define HQ 1024
#define ZQ 256
#define G4H (4 * HQ)
#define NBLK 128          // persistent grid size
#define BHSZ ((size_t)BQ * HQ)

// ---------------------------------------------------------------------------
// Static device scratch
// ---------------------------------------------------------------------------
__device__ float g_X[(size_t)LQ * BQ * HQ];    // precomputed tanh(input proj)
__device__ float g_WpT[(size_t)VQ * HQ];
__device__ int   g_idx[LQ * BQ];
__device__ uint2 g_sk[LQ];
__device__ float g_h0[2 * BQ * HQ];            // parity double buffer
__device__ float g_h1[2 * BQ * HQ];
__device__ float g_Wi0p[(size_t)G4H * HQ];     // gate-interleaved weights
__device__ float g_Wh0p[(size_t)G4H * HQ];
__device__ float g_Wi1p[(size_t)G4H * HQ];
__device__ float g_Wh1p[(size_t)G4H * HQ];
__device__ float g_b0p[G4H];                   // combined interleaved biases
__device__ float g_b1p[G4H];
__device__ float g_parts[8 * BQ * VQ];         // logits split-K partials
__device__ unsigned g_count;                   // grid barrier counter

// ---------------------------------------------------------------------------
// Threefry2x32 (JAX partitionable layout)
// ---------------------------------------------------------------------------
static __device__ __forceinline__ uint32_t rotl32(uint32_t x, int r) {
    return (x << r) | (x >> (32 - r));
}
static __device__ __forceinline__ void tf_round4(uint32_t& x0, uint32_t& x1,
                                                 int r0, int r1, int r2, int r3) {
    x0 += x1; x1 = rotl32(x1, r0); x1 ^= x0;
    x0 += x1; x1 = rotl32(x1, r1); x1 ^= x0;
    x0 += x1; x1 = rotl32(x1, r2); x1 ^= x0;
    x0 += x1; x1 = rotl32(x1, r3); x1 ^= x0;
}
static __device__ __forceinline__ uint2 threefry2x32(uint32_t k0, uint32_t k1,
                                                     uint32_t c0, uint32_t c1) {
    uint32_t ks2 = k0 ^ k1 ^ 0x1BD11BDAu;
    uint32_t x0 = c0 + k0, x1 = c1 + k1;
    tf_round4(x0, x1, 13, 15, 26, 6);  x0 += k1;  x1 += ks2 + 1u;
    tf_round4(x0, x1, 17, 29, 16, 24); x0 += ks2; x1 += k0 + 2u;
    tf_round4(x0, x1, 13, 15, 26, 6);  x0 += k0;  x1 += k1 + 3u;
    tf_round4(x0, x1, 17, 29, 16, 24); x0 += k1;  x1 += ks2 + 4u;
    tf_round4(x0, x1, 13, 15, 26, 6);  x0 += ks2; x1 += k0 + 5u;
    return make_uint2(x0, x1);
}

// key chain (partitionable split): new_key = tf(key,(0,0)), subkey = tf(key,(0,1))
// Also resets the grid-barrier counter each launch.
__global__ void key_chain_kernel(uint2* sk_out) {
    if (threadIdx.x == 0 && blockIdx.x == 0) {
        g_count = 0u;
        uint32_t k0 = 0u, k1 = 42u;
        for (int t = 0; t < LQ; ++t) {
            uint2 nk = threefry2x32(k0, k1, 0u, 0u);
            uint2 s  = threefry2x32(k0, k1, 0u, 1u);
            sk_out[t] = s;
            k0 = nk.x; k1 = nk.y;
        }
    }
}

// ---------------------------------------------------------------------------
// Setup kernels
// ---------------------------------------------------------------------------
__global__ void find_idx_kernel(const float* __restrict__ targets, int* __restrict__ idx) {
    int row  = blockIdx.x * 8 + (threadIdx.x >> 5);
    int lane = threadIdx.x & 31;
    const float* r = targets + (size_t)row * VQ;
    int found = 0;
    for (int j = lane; j < VQ; j += 32)
        if (r[j] > 0.5f) found = j;
#pragma unroll
    for (int o = 16; o; o >>= 1)
        found = max(found, __shfl_xor_sync(0xFFFFFFFFu, found, o));
    if (lane == 0) idx[row] = found;
}

__global__ void transpose_wp_kernel(const float* __restrict__ Wp, float* __restrict__ WpT) {
    __shared__ float tile[32][33];
    int x  = blockIdx.x * 32 + threadIdx.x;   // V index
    int y0 = blockIdx.y * 32;                 // H base
#pragma unroll
    for (int i = 0; i < 32; i += 8)
        tile[threadIdx.y + i][threadIdx.x] = Wp[(size_t)(y0 + threadIdx.y + i) * VQ + x];
    __syncthreads();
    int v0 = blockIdx.x * 32;
    int h  = y0 + threadIdx.x;
#pragma unroll
    for (int i = 0; i < 32; i += 8)
        WpT[(size_t)(v0 + threadIdx.y + i) * HQ + h] = tile[threadIdx.x][threadIdx.y + i];
}

__global__ void init_h_kernel(const float* __restrict__ z, const float* __restrict__ Whz,
                              const float* __restrict__ bhz, float* __restrict__ h) {
    int i  = blockIdx.x * blockDim.x + threadIdx.x;   // B*H
    int b  = i >> 10;
    int hh = i & (HQ - 1);
    const float4* zr = (const float4*)(z + (size_t)b * ZQ);
    const float4* w  = (const float4*)(Whz + (size_t)hh * ZQ);
    float acc = 0.f;
#pragma unroll 4
    for (int k = 0; k < ZQ / 4; ++k) {
        float4 a = zr[k], q = w[k];
        acc += a.x * q.x + a.y * q.y + a.z * q.z + a.w * q.w;
    }
    h[i] = tanhf(acc + bhz[hh]);
}

// X[t,b,h] = tanh(bp[h] + (t>0 ? WpT[idx[t-1,b]][h] : 0))
__global__ void build_x_kernel(const float* __restrict__ WpT, const float* __restrict__ bp,
                               const int* __restrict__ idx, float* __restrict__ X) {
    size_t i  = (size_t)blockIdx.x * blockDim.x + threadIdx.x;
    int    h  = (int)(i & (HQ - 1));
    size_t tb = i >> 10;
    float v = bp[h];
    if (tb >= BQ) {
        int tok = idx[tb - BQ];
        v += WpT[(size_t)tok * HQ + h];
    }
    X[i] = tanhf(v);
}

// Interleave gate weights: out row r = 4h+g  <-  in row g*H+h  (torch order i,f,g,o)
__global__ void interleave_kernel(
    const float* __restrict__ Wi0, const float* __restrict__ Wh0,
    const float* __restrict__ bi0, const float* __restrict__ bh0,
    const float* __restrict__ Wi1, const float* __restrict__ Wh1,
    const float* __restrict__ bi1, const float* __restrict__ bh1,
    float* __restrict__ Wi0p, float* __restrict__ Wh0p, float* __restrict__ b0p,
    float* __restrict__ Wi1p, float* __restrict__ Wh1p, float* __restrict__ b1p) {
    size_t i = (size_t)blockIdx.x * 256 + threadIdx.x;   // 4 * 4M elements
    int mat = (int)(i >> 22);
    size_t rem = i & ((1u << 22) - 1);
    int r = (int)(rem >> 10), col = (int)(rem & 1023);
    int h = r >> 2, g = r & 3;
    size_t src = (size_t)(g * HQ + h) * HQ + col;
    size_t dst = (size_t)r * HQ + col;
    if      (mat == 0) Wi0p[dst] = Wi0[src];
    else if (mat == 1) Wh0p[dst] = Wh0[src];
    else if (mat == 2) Wi1p[dst] = Wi1[src];
    else               Wh1p[dst] = Wh1[src];
    if (i < 2 * G4H) {
        int layer = (int)(i >> 12);
        int rr = (int)(i & (G4H - 1));
        int hh = rr >> 2, gg = rr & 3;
        int so = gg * HQ + hh;
        if (layer == 0) b0p[rr] = bi0[so] + bh0[so];
        else            b1p[rr] = bi1[so] + bh1[so];
    }
}

// ---------------------------------------------------------------------------
// Persistent decode kernel: 128 blocks x 256 threads
// ---------------------------------------------------------------------------
static __device__ __forceinline__ float sigmoidf_(float x) {
    return 1.0f / (1.0f + expf(-x));
}

static __device__ __forceinline__ void grid_barrier(unsigned& epoch) {
    __syncthreads();
    ++epoch;
    if (threadIdx.x == 0) {
        __threadfence();                       // release (+ flush)
        atomicAdd(&g_count, 1u);
        volatile unsigned* vc = &g_count;
        unsigned target = epoch * (unsigned)NBLK;
        while (*vc < target) {}
        __threadfence();                       // acquire: CCTL.IVALL invalidates L1
    }
    __syncthreads();
}

// 64(M) x 128(N) tile GEMM: acc = A1[64,K1]*B1^T + A2[64,K2]*B2^T
// A via __ldcg (cross-step data), B via __ldg (weights).
static __device__ __forceinline__ void gemm_tile(
    const float* __restrict__ A1, const float* __restrict__ B1, int K1,
    const float* __restrict__ A2, const float* __restrict__ B2, int K2,
    int m0, int n0, float (&acc)[4][8],
    float (&As)[2][8][64], float (&Bs)[2][8][128]) {
    const int tid  = threadIdx.x;
    const int arow = tid >> 1, acol = (tid & 1) * 4;   // tid<128 loads A
    const int bn   = tid & 127, bkh = (tid >> 7) * 4;
    const int tx   = tid & 15,  ty  = tid >> 4;

#pragma unroll
    for (int i = 0; i < 4; ++i)
#pragma unroll
        for (int j = 0; j < 8; ++j) acc[i][j] = 0.f;

#pragma unroll 1
    for (int seg = 0; seg < 2; ++seg) {
        const float* A = seg ? A2 : A1;
        const float* B = seg ? B2 : B1;
        const int K = seg ? K2 : K1;
        if (A == nullptr || K == 0) continue;
        const float* aP = A + (size_t)(m0 + arow) * HQ + acol;
        const float* bP = B + (size_t)(n0 + bn) * HQ + bkh;

        __syncthreads();
        if (tid < 128) {
            float4 a4 = __ldcg((const float4*)aP);
            As[0][acol + 0][arow] = a4.x; As[0][acol + 1][arow] = a4.y;
            As[0][acol + 2][arow] = a4.z; As[0][acol + 3][arow] = a4.w;
        }
        {
            float4 b4 = __ldg((const float4*)bP);
            Bs[0][bkh + 0][bn] = b4.x; Bs[0][bkh + 1][bn] = b4.y;
            Bs[0][bkh + 2][bn] = b4.z; Bs[0][bkh + 3][bn] = b4.w;
        }
        __syncthreads();

        const int nsteps = K >> 3;
        for (int s = 0; s < nsteps; ++s) {
            const int cur = s & 1;
            float4 a4, b4;
            const bool hn = (s + 1 < nsteps);
            if (hn) {
                if (tid < 128) a4 = __ldcg((const float4*)(aP + (s + 1) * 8));
                b4 = __ldg((const float4*)(bP + (s + 1) * 8));
            }
#pragma unroll
            for (int kk = 0; kk < 8; ++kk) {
                float4 aa  = *(const float4*)&As[cur][kk][ty * 4];
                float4 b0v = *(const float4*)&Bs[cur][kk][tx * 8];
                float4 b1v = *(const float4*)&Bs[cur][kk][tx * 8 + 4];
                float av[4] = {aa.x, aa.y, aa.z, aa.w};
                float bv[8] = {b0v.x, b0v.y, b0v.z, b0v.w, b1v.x, b1v.y, b1v.z, b1v.w};
#pragma unroll
                for (int i = 0; i < 4; ++i)
#pragma unroll
                    for (int j = 0; j < 8; ++j)
                        acc[i][j] = fmaf(av[i], bv[j], acc[i][j]);
            }
            if (hn) {
                const int nxt = cur ^ 1;
                if (tid < 128) {
                    As[nxt][acol + 0][arow] = a4.x; As[nxt][acol + 1][arow] = a4.y;
                    As[nxt][acol + 2][arow] = a4.z; As[nxt][acol + 3][arow] = a4.w;
                }
                Bs[nxt][bkh + 0][bn] = b4.x; Bs[nxt][bkh + 1][bn] = b4.y;
                Bs[nxt][bkh + 2][bn] = b4.z; Bs[nxt][bkh + 3][bn] = b4.w;
                __syncthreads();
            }
        }
    }
}

__global__ void __launch_bounds__(256, 1)
decode_kernel(const float* __restrict__ X,
              float* __restrict__ h0b, float* __restrict__ h1b,
              const float* __restrict__ Wi0p, const float* __restrict__ Wh0p,
              const float* __restrict__ b0p,
              const float* __restrict__ Wi1p, const float* __restrict__ Wh1p,
              const float* __restrict__ b1p,
              const float* __restrict__ Wout, const float* __restrict__ bout,
              float* __restrict__ parts, const uint2* __restrict__ sks,
              float* __restrict__ out_s, float* __restrict__ out_l) {
    __shared__ float As[2][8][64];
    __shared__ float Bs[2][8][128];
    __shared__ float sv[256];
    __shared__ int   si[256];

    const int blk = blockIdx.x, tid = threadIdx.x;
    const int tx = tid & 15, ty = tid >> 4;
    const int gby = blk >> 5, gbx = blk & 31;                  // gates: 4 x 32 tiles
    const int lm = blk >> 5, ln = (blk >> 3) & 3, lk = blk & 7; // logits: 4 x 4 x 8

    unsigned epoch = 0;
    float c0r[4][2] = {{0.f, 0.f}, {0.f, 0.f}, {0.f, 0.f}, {0.f, 0.f}};
    float c1r[4][2] = {{0.f, 0.f}, {0.f, 0.f}, {0.f, 0.f}, {0.f, 0.f}};
    float acc[4][8];

    for (int t = 0; t < LQ; ++t) {
        const int p = t & 1;
        const float* h0cur = h0b + (size_t)p * BHSZ;
        float*       h0nxt = h0b + (size_t)(p ^ 1) * BHSZ;
        const float* h1cur = h1b + (size_t)p * BHSZ;
        float*       h1nxt = h1b + (size_t)(p ^ 1) * BHSZ;

        // ---- Phase A: layer-0 gates + fused cell update ----
        gemm_tile(X + (size_t)t * BHSZ, Wi0p, HQ, h0cur, Wh0p, HQ,
                  gby * 64, gbx * 128, acc, As, Bs);
#pragma unroll
        for (int i = 0; i < 4; ++i) {
            const int b = gby * 64 + ty * 4 + i;
#pragma unroll
            for (int u = 0; u < 2; ++u) {
                const int r = gbx * 128 + tx * 8 + u * 4;
                float ig = sigmoidf_(acc[i][u * 4 + 0] + b0p[r + 0]);
                float fg = sigmoidf_(acc[i][u * 4 + 1] + b0p[r + 1]);
                float gg = tanhf(acc[i][u * 4 + 2] + b0p[r + 2]);
                float og = sigmoidf_(acc[i][u * 4 + 3] + b0p[r + 3]);
                float cn = fg * c0r[i][u] + ig * gg;
                c0r[i][u] = cn;
                h0nxt[(size_t)b * HQ + (r >> 2)] = og * tanhf(cn);
            }
        }
        grid_barrier(epoch);

        // ---- Phase B: layer-1 gates + fused cell update ----
        gemm_tile(h0nxt, Wi1p, HQ, h1cur, Wh1p, HQ,
                  gby * 64, gbx * 128, acc, As, Bs);
#pragma unroll
        for (int i = 0; i < 4; ++i) {
            const int b = gby * 64 + ty * 4 + i;
#pragma unroll
            for (int u = 0; u < 2; ++u) {
                const int r = gbx * 128 + tx * 8 + u * 4;
                float ig = sigmoidf_(acc[i][u * 4 + 0] + b1p[r + 0]);
                float fg = sigmoidf_(acc[i][u * 4 + 1] + b1p[r + 1]);
                float gg = tanhf(acc[i][u * 4 + 2] + b1p[r + 2]);
                float og = sigmoidf_(acc[i][u * 4 + 3] + b1p[r + 3]);
                float cn = fg * c1r[i][u] + ig * gg;
                c1r[i][u] = cn;
                h1nxt[(size_t)b * HQ + (r >> 2)] = og * tanhf(cn);
            }
        }
        grid_barrier(epoch);

        // ---- Phase C: logits partials (split-K over 8 slices of 128) ----
        gemm_tile(h1nxt + lk * 128, Wout + lk * 128, 128, nullptr, nullptr, 0,
                  lm * 64, ln * 128, acc, As, Bs);
        {
            float* P = parts + (size_t)lk * BQ * VQ;
#pragma unroll
            for (int i = 0; i < 4; ++i) {
                const int row = lm * 64 + ty * 4 + i;
                float* cr = P + (size_t)row * VQ + ln * 128 + tx * 8;
                *(float4*)(cr)     = make_float4(acc[i][0], acc[i][1], acc[i][2], acc[i][3]);
                *(float4*)(cr + 4) = make_float4(acc[i][4], acc[i][5], acc[i][6], acc[i][7]);
            }
        }
        grid_barrier(epoch);

        // ---- Phase S: reduce partials, gumbel-argmax sample (overlaps next A) ----
        {
            const int r0   = blk * 2 + (tid >> 7);   // batch row 0..255
            const int lane = tid & 127;
            const uint2 sk = sks[t];
            float best = -3.4e38f;
            int   bidx = 1 << 30;
            for (int v = lane; v < VQ; v += 128) {
                const int o = r0 * VQ + v;
                float lg = bout[v];
#pragma unroll
                for (int s = 0; s < 8; ++s)
                    lg += __ldcg(&parts[(size_t)s * BQ * VQ + o]);
                if (out_l) out_l[(size_t)t * BQ * VQ + o] = lg;
                uint2 rr = threefry2x32(sk.x, sk.y, 0u, (uint32_t)o);
                uint32_t bits = rr.x ^ rr.y;
                float f = __uint_as_float((bits >> 9) | 0x3f800000u) - 1.0f;
                float u = fmaxf(1.17549435e-38f, f);
                float gum = -logf(-logf(u));
                float val = lg + gum;
                if (val > best) { best = val; bidx = v; }
                else if (val == best && v < bidx) { bidx = v; }
            }
            sv[tid] = best; si[tid] = bidx;
            __syncthreads();
            for (int o = 64; o > 0; o >>= 1) {
                if ((tid & 127) < o) {
                    float v2 = sv[tid + o]; int i2 = si[tid + o];
                    if (v2 > sv[tid] || (v2 == sv[tid] && i2 < si[tid])) {
                        sv[tid] = v2; si[tid] = i2;
                    }
                }
                __syncthreads();
            }
            if ((tid & 127) == 0 && out_s) out_s[(size_t)t * BQ + r0] = (float)si[tid];
            __syncthreads();
        }
        // no barrier needed here: next Phase A touches neither parts nor sample smem
    }
}

// ---------------------------------------------------------------------------
// Host launch
// ---------------------------------------------------------------------------
extern "C" void kernel_launch(void* const* d_in, const int* in_sizes, int n_in,
                              void* d_out, int out_size) {
    const float* z    = (const float*)d_in[0];
    const float* tgt  = (const float*)d_in[1];
    const float* Wp   = (const float*)d_in[2];
    const float* bp   = (const float*)d_in[3];
    const float* Wi0  = (const float*)d_in[4];
    const float* Wh0  = (const float*)d_in[5];
    const float* bi0  = (const float*)d_in[6];
    const float* bh0  = (const float*)d_in[7];
    const float* Wi1  = (const float*)d_in[8];
    const float* Wh1  = (const float*)d_in[9];
    const float* bi1  = (const float*)d_in[10];
    const float* bh1  = (const float*)d_in[11];
    const float* Whz0 = (const float*)d_in[12];
    const float* bhz0 = (const float*)d_in[13];
    const float* Whz1 = (const float*)d_in[14];
    const float* bhz1 = (const float*)d_in[15];
    const float* Wout = (const float*)d_in[16];
    const float* bout = (const float*)d_in[17];

    float *pX, *pWpT, *ph0, *ph1, *pWi0p, *pWh0p, *pWi1p, *pWh1p, *pb0p, *pb1p, *pparts;
    int* pidx;
    uint2* psk;
    cudaGetSymbolAddress((void**)&pX, g_X);
    cudaGetSymbolAddress((void**)&pWpT, g_WpT);
    cudaGetSymbolAddress((void**)&pidx, g_idx);
    cudaGetSymbolAddress((void**)&psk, g_sk);
    cudaGetSymbolAddress((void**)&ph0, g_h0);
    cudaGetSymbolAddress((void**)&ph1, g_h1);
    cudaGetSymbolAddress((void**)&pWi0p, g_Wi0p);
    cudaGetSymbolAddress((void**)&pWh0p, g_Wh0p);
    cudaGetSymbolAddress((void**)&pWi1p, g_Wi1p);
    cudaGetSymbolAddress((void**)&pWh1p, g_Wh1p);
    cudaGetSymbolAddress((void**)&pb0p, g_b0p);
    cudaGetSymbolAddress((void**)&pb1p, g_b1p);
    cudaGetSymbolAddress((void**)&pparts, g_parts);

    // output layout: samples [L,B] then logits [L,B,V] as float32
    const size_t LB  = (size_t)LQ * BQ;
    const size_t LBV = LB * VQ;
    float* out = (float*)d_out;
    float* out_samples = nullptr;
    float* out_logits  = nullptr;
    if ((size_t)out_size == LB + LBV) { out_samples = out; out_logits = out + LB; }
    else if ((size_t)out_size == LBV) { out_logits = out; }
    else                              { out_samples = out; }

    // ---- setup (8 nodes) ----
    find_idx_kernel<<<(LQ * BQ) / 8, 256>>>(tgt, pidx);
    transpose_wp_kernel<<<dim3(VQ / 32, HQ / 32), dim3(32, 8)>>>(Wp, pWpT);
    key_chain_kernel<<<1, 32>>>(psk);                    // also resets g_count
    init_h_kernel<<<(BQ * HQ) / 256, 256>>>(z, Whz0, bhz0, ph0);   // parity-0 buffers
    init_h_kernel<<<(BQ * HQ) / 256, 256>>>(z, Whz1, bhz1, ph1);
    build_x_kernel<<<(unsigned)(((size_t)LQ * BQ * HQ) / 256), 256>>>(pWpT, bp, pidx, pX);
    interleave_kernel<<<(unsigned)(((size_t)4 * G4H * HQ) / 256), 256>>>(
        Wi0, Wh0, bi0, bh0, Wi1, Wh1, bi1, bh1,
        pWi0p, pWh0p, pb0p, pWi1p, pWh1p, pb1p);

    // ---- persistent decode (1 node) ----
    decode_kernel<<<NBLK, 256>>>(pX, ph0, ph1,
                                 pWi0p, pWh0p, pb0p,
                                 pWi1p, pWh1p, pb1p,
                                 Wout, bout, pparts, psk,
                                 out_samples, out_logits);
}

// round 9
// speedup vs baseline: 2.4630x; 2.4630x over previous
#include <cuda_runtime.h>
#include <cstdint>
#include <cstddef>

// ---------------------------------------------------------------------------
// Problem dims
// ---------------------------------------------------------------------------
#define LQ 281
#define BQ 256
#define VQ 512
#define HQ 1024
#define ZQ 256
#define G4H (4 * HQ)
#define NBLK 128
#define BHSZ ((size_t)BQ * HQ)

// ---------------------------------------------------------------------------
// Static device scratch
// ---------------------------------------------------------------------------
__device__ float g_X[(size_t)LQ * BQ * HQ];    // precomputed tanh(input proj)
__device__ float g_WpT[(size_t)VQ * HQ];
__device__ int   g_idx[LQ * BQ];
__device__ uint2 g_sk[LQ];
__device__ float g_h0[2 * BQ * HQ];            // parity double buffer
__device__ float g_h1[2 * BQ * HQ];
__device__ float g_Wi0p[(size_t)G4H * HQ];     // gate-interleaved weights (fp32)
__device__ float g_Wh0p[(size_t)G4H * HQ];
__device__ float g_Wi1p[(size_t)G4H * HQ];
__device__ float g_Wh1p[(size_t)G4H * HQ];
__device__ float g_b0p[G4H];
__device__ float g_b1p[G4H];
__device__ float g_parts[8 * BQ * VQ];
__device__ unsigned g_count;

// ---------------------------------------------------------------------------
// Threefry2x32 (JAX partitionable layout) -- verified exact by R2 pass
// ---------------------------------------------------------------------------
static __device__ __forceinline__ uint32_t rotl32(uint32_t x, int r) {
    return (x << r) | (x >> (32 - r));
}
static __device__ __forceinline__ void tf_round4(uint32_t& x0, uint32_t& x1,
                                                 int r0, int r1, int r2, int r3) {
    x0 += x1; x1 = rotl32(x1, r0); x1 ^= x0;
    x0 += x1; x1 = rotl32(x1, r1); x1 ^= x0;
    x0 += x1; x1 = rotl32(x1, r2); x1 ^= x0;
    x0 += x1; x1 = rotl32(x1, r3); x1 ^= x0;
}
static __device__ __forceinline__ uint2 threefry2x32(uint32_t k0, uint32_t k1,
                                                     uint32_t c0, uint32_t c1) {
    uint32_t ks2 = k0 ^ k1 ^ 0x1BD11BDAu;
    uint32_t x0 = c0 + k0, x1 = c1 + k1;
    tf_round4(x0, x1, 13, 15, 26, 6);  x0 += k1;  x1 += ks2 + 1u;
    tf_round4(x0, x1, 17, 29, 16, 24); x0 += ks2; x1 += k0 + 2u;
    tf_round4(x0, x1, 13, 15, 26, 6);  x0 += k0;  x1 += k1 + 3u;
    tf_round4(x0, x1, 17, 29, 16, 24); x0 += k1;  x1 += ks2 + 4u;
    tf_round4(x0, x1, 13, 15, 26, 6);  x0 += ks2; x1 += k0 + 5u;
    return make_uint2(x0, x1);
}

__global__ void key_chain_kernel(uint2* sk_out) {
    if (threadIdx.x == 0 && blockIdx.x == 0) {
        g_count = 0u;
        uint32_t k0 = 0u, k1 = 42u;
        for (int t = 0; t < LQ; ++t) {
            uint2 nk = threefry2x32(k0, k1, 0u, 0u);
            uint2 s  = threefry2x32(k0, k1, 0u, 1u);
            sk_out[t] = s;
            k0 = nk.x; k1 = nk.y;
        }
    }
}

// ---------------------------------------------------------------------------
// Setup kernels (unchanged from passing R2)
// ---------------------------------------------------------------------------
__global__ void find_idx_kernel(const float* __restrict__ targets, int* __restrict__ idx) {
    int row  = blockIdx.x * 8 + (threadIdx.x >> 5);
    int lane = threadIdx.x & 31;
    const float* r = targets + (size_t)row * VQ;
    int found = 0;
    for (int j = lane; j < VQ; j += 32)
        if (r[j] > 0.5f) found = j;
#pragma unroll
    for (int o = 16; o; o >>= 1)
        found = max(found, __shfl_xor_sync(0xFFFFFFFFu, found, o));
    if (lane == 0) idx[row] = found;
}

__global__ void transpose_wp_kernel(const float* __restrict__ Wp, float* __restrict__ WpT) {
    __shared__ float tile[32][33];
    int x  = blockIdx.x * 32 + threadIdx.x;
    int y0 = blockIdx.y * 32;
#pragma unroll
    for (int i = 0; i < 32; i += 8)
        tile[threadIdx.y + i][threadIdx.x] = Wp[(size_t)(y0 + threadIdx.y + i) * VQ + x];
    __syncthreads();
    int v0 = blockIdx.x * 32;
    int h  = y0 + threadIdx.x;
#pragma unroll
    for (int i = 0; i < 32; i += 8)
        WpT[(size_t)(v0 + threadIdx.y + i) * HQ + h] = tile[threadIdx.x][threadIdx.y + i];
}

__global__ void init_h_kernel(const float* __restrict__ z, const float* __restrict__ Whz,
                              const float* __restrict__ bhz, float* __restrict__ h) {
    int i  = blockIdx.x * blockDim.x + threadIdx.x;
    int b  = i >> 10;
    int hh = i & (HQ - 1);
    const float4* zr = (const float4*)(z + (size_t)b * ZQ);
    const float4* w  = (const float4*)(Whz + (size_t)hh * ZQ);
    float acc = 0.f;
#pragma unroll 4
    for (int k = 0; k < ZQ / 4; ++k) {
        float4 a = zr[k], q = w[k];
        acc += a.x * q.x + a.y * q.y + a.z * q.z + a.w * q.w;
    }
    h[i] = tanhf(acc + bhz[hh]);
}

__global__ void build_x_kernel(const float* __restrict__ WpT, const float* __restrict__ bp,
                               const int* __restrict__ idx, float* __restrict__ X) {
    size_t i  = (size_t)blockIdx.x * blockDim.x + threadIdx.x;
    int    h  = (int)(i & (HQ - 1));
    size_t tb = i >> 10;
    float v = bp[h];
    if (tb >= BQ) {
        int tok = idx[tb - BQ];
        v += WpT[(size_t)tok * HQ + h];
    }
    X[i] = tanhf(v);
}

// Interleave gate weights: out row r = 4h+g  <-  in row g*H+h  (torch order i,f,g,o)
__global__ void interleave_kernel(
    const float* __restrict__ Wi0, const float* __restrict__ Wh0,
    const float* __restrict__ bi0, const float* __restrict__ bh0,
    const float* __restrict__ Wi1, const float* __restrict__ Wh1,
    const float* __restrict__ bi1, const float* __restrict__ bh1,
    float* __restrict__ Wi0p, float* __restrict__ Wh0p, float* __restrict__ b0p,
    float* __restrict__ Wi1p, float* __restrict__ Wh1p, float* __restrict__ b1p) {
    size_t i = (size_t)blockIdx.x * 256 + threadIdx.x;
    int mat = (int)(i >> 22);
    size_t rem = i & ((1u << 22) - 1);
    int r = (int)(rem >> 10), col = (int)(rem & 1023);
    int h = r >> 2, g = r & 3;
    size_t src = (size_t)(g * HQ + h) * HQ + col;
    size_t dst = (size_t)r * HQ + col;
    if      (mat == 0) Wi0p[dst] = Wi0[src];
    else if (mat == 1) Wh0p[dst] = Wh0[src];
    else if (mat == 2) Wi1p[dst] = Wi1[src];
    else               Wh1p[dst] = Wh1[src];
    if (i < 2 * G4H) {
        int layer = (int)(i >> 12);
        int rr = (int)(i & (G4H - 1));
        int hh = rr >> 2, gg = rr & 3;
        int so = gg * HQ + hh;
        if (layer == 0) b0p[rr] = bi0[so] + bh0[so];
        else            b1p[rr] = bi1[so] + bh1[so];
    }
}

// ---------------------------------------------------------------------------
// Persistent decode kernel: mma.sync tf32x3 GEMM
// ---------------------------------------------------------------------------
static __device__ __forceinline__ float sigmoidf_(float x) {
    return 1.0f / (1.0f + expf(-x));
}

static __device__ __forceinline__ void grid_barrier(unsigned& epoch) {
    __syncthreads();
    ++epoch;
    if (threadIdx.x == 0) {
        __threadfence();
        atomicAdd(&g_count, 1u);
        volatile unsigned* vc = &g_count;
        unsigned target = epoch * (unsigned)NBLK;
        while (*vc < target) {}
        __threadfence();
    }
    __syncthreads();
}

// round-to-nearest tf32 hi/lo split
static __device__ __forceinline__ void split1(float x, float& h, float& l) {
    uint32_t u = __float_as_uint(x);
    h = __uint_as_float((u + 0x1000u) & 0xFFFFE000u);
    l = x - h;
}
static __device__ __forceinline__ void split4(float4 v, float4& h, float4& l) {
    split1(v.x, h.x, l.x); split1(v.y, h.y, l.y);
    split1(v.z, h.z, l.z); split1(v.w, h.w, l.w);
}

static __device__ __forceinline__ void mma_tf32(float* d, const uint32_t* a,
                                                const uint32_t* b) {
    asm volatile(
        "mma.sync.aligned.m16n8k8.row.col.f32.tf32.tf32.f32 "
        "{%0,%1,%2,%3}, {%4,%5,%6,%7}, {%8,%9}, {%0,%1,%2,%3};"
        : "+f"(d[0]), "+f"(d[1]), "+f"(d[2]), "+f"(d[3])
        : "r"(a[0]), "r"(a[1]), "r"(a[2]), "r"(a[3]), "r"(b[0]), "r"(b[1]));
}

// Smem stage: Ah[64x36] Al[64x36] Bh[128x36] Bl[128x36]  (floats)
#define ASTRIDE 36
#define STG_FLOATS 13824   // 2304 + 2304 + 4608 + 4608
#define DYN_SMEM (2 * STG_FLOATS * 4)

// C[64,128] = A1[64xK1]*B1^T + A2[64xK2]*B2^T  (tf32x3, K chunks of 32)
static __device__ __forceinline__ void gemm_mma(
    const float* __restrict__ A1, const float* __restrict__ B1, int nch1,
    const float* __restrict__ A2, const float* __restrict__ B2, int nch2,
    int koff, int m0, int n0, float* sm, float (&acc)[2][4][4]) {
    const int tid = threadIdx.x;
    const int lid = tid & 31;
    const int wid = tid >> 5;
    const int warp_m = wid >> 2, warp_n = wid & 3;
    const int quad = lid >> 2, qi = lid & 3;
    const int arow = tid >> 2, aq = tid & 3;
    const int brow = tid >> 1, bq = (tid & 1) * 4;

#pragma unroll
    for (int i = 0; i < 2; ++i)
#pragma unroll
        for (int j = 0; j < 4; ++j)
#pragma unroll
            for (int k = 0; k < 4; ++k) acc[i][j][k] = 0.f;

    const int total = nch1 + nch2;
    float4 ra[2], rb[4];

    auto ldg_chunk = [&](int c) {
        const float* A = (c < nch1) ? A1 : A2;
        const float* B = (c < nch1) ? B1 : B2;
        const int kb = koff + ((c < nch1) ? c : c - nch1) * 32;
        const float* ap = A + (size_t)(m0 + arow) * HQ + kb;
        const float* bp = B + (size_t)(n0 + brow) * HQ + kb;
#pragma unroll
        for (int j = 0; j < 2; ++j)
            ra[j] = __ldcg((const float4*)(ap + (aq + j * 4) * 4));
#pragma unroll
        for (int j = 0; j < 4; ++j)
            rb[j] = __ldg((const float4*)(bp + (bq + j) * 4));
    };

    auto sts_chunk = [&](int s) {
        float* Ah = sm + s * STG_FLOATS;
        float* Al = Ah + 2304;
        float* Bh = Ah + 4608;
        float* Bl = Ah + 9216;
#pragma unroll
        for (int j = 0; j < 2; ++j) {
            float4 hi, lo;
            split4(ra[j], hi, lo);
            const int cw = arow * ASTRIDE + (aq + j * 4) * 4;
            *(float4*)(Ah + cw) = hi;
            *(float4*)(Al + cw) = lo;
        }
#pragma unroll
        for (int j = 0; j < 4; ++j) {
            float4 hi, lo;
            split4(rb[j], hi, lo);
            const int cw = brow * ASTRIDE + (bq + j) * 4;
            *(float4*)(Bh + cw) = hi;
            *(float4*)(Bl + cw) = lo;
        }
    };

    auto compute = [&](int s) {
        const float* Ah = sm + s * STG_FLOATS;
        const float* Al = Ah + 2304;
        const float* Bh = Ah + 4608;
        const float* Bl = Ah + 9216;
#pragma unroll
        for (int k8 = 0; k8 < 4; ++k8) {
            const int kb = k8 * 8;
            uint32_t ah[2][4], al[2][4], bh[4][2], bl[4][2];
#pragma unroll
            for (int mt = 0; mt < 2; ++mt) {
                const int rr = warp_m * 32 + mt * 16 + quad;
                const int c0 = rr * ASTRIDE + kb + qi;
                const int c1 = (rr + 8) * ASTRIDE + kb + qi;
                ah[mt][0] = __float_as_uint(Ah[c0]);
                ah[mt][1] = __float_as_uint(Ah[c1]);
                ah[mt][2] = __float_as_uint(Ah[c0 + 4]);
                ah[mt][3] = __float_as_uint(Ah[c1 + 4]);
                al[mt][0] = __float_as_uint(Al[c0]);
                al[mt][1] = __float_as_uint(Al[c1]);
                al[mt][2] = __float_as_uint(Al[c0 + 4]);
                al[mt][3] = __float_as_uint(Al[c1 + 4]);
            }
#pragma unroll
            for (int nt = 0; nt < 4; ++nt) {
                const int nn = warp_n * 32 + nt * 8 + quad;
                const int c = nn * ASTRIDE + kb + qi;
                bh[nt][0] = __float_as_uint(Bh[c]);
                bh[nt][1] = __float_as_uint(Bh[c + 4]);
                bl[nt][0] = __float_as_uint(Bl[c]);
                bl[nt][1] = __float_as_uint(Bl[c + 4]);
            }
#pragma unroll
            for (int mt = 0; mt < 2; ++mt)
#pragma unroll
                for (int nt = 0; nt < 4; ++nt) {
                    mma_tf32(acc[mt][nt], ah[mt], bh[nt]);
                    mma_tf32(acc[mt][nt], ah[mt], bl[nt]);
                    mma_tf32(acc[mt][nt], al[mt], bh[nt]);
                }
        }
    };

    ldg_chunk(0);
    sts_chunk(0);
    __syncthreads();
    for (int c = 0; c < total; ++c) {
        const bool hn = (c + 1 < total);
        if (hn) ldg_chunk(c + 1);
        compute(c & 1);
        __syncthreads();
        if (hn) { sts_chunk((c + 1) & 1); __syncthreads(); }
    }
}

// Fused LSTM cell epilogue over mma fragments (gate-interleaved cols)
static __device__ __forceinline__ void lstm_epilogue(
    float (&acc)[2][4][4], const float* __restrict__ s_b, float (&cr)[8],
    float* __restrict__ hout, int gby, int gbn,
    int warp_m, int warp_n, int quad, int qi) {
    const int odd = qi & 1;
#pragma unroll
    for (int mt = 0; mt < 2; ++mt)
#pragma unroll
        for (int nt = 0; nt < 4; ++nt) {
            float* d = acc[mt][nt];
            float s0 = odd ? d[0] : d[2];
            float s1 = odd ? d[1] : d[3];
            float r0 = __shfl_xor_sync(0xFFFFFFFFu, s0, 1);
            float r1 = __shfl_xor_sync(0xFFFFFFFFu, s1, 1);
            float gi, gf, gg, go;
            int ro;
            if (!odd) { gi = d[0]; gf = d[1]; gg = r0;   go = r1;   ro = 0; }
            else      { gi = r0;   gf = r1;   gg = d[2]; go = d[3]; ro = 8; }
            const int hloc = warp_n * 8 + nt * 2 + (qi >> 1);
            float I = sigmoidf_(gi + s_b[hloc * 4 + 0]);
            float F = sigmoidf_(gf + s_b[hloc * 4 + 1]);
            float G = tanhf(gg + s_b[hloc * 4 + 2]);
            float O = sigmoidf_(go + s_b[hloc * 4 + 3]);
            const int ci = mt * 4 + nt;
            float cn = F * cr[ci] + I * G;
            cr[ci] = cn;
            const int b = gby * 64 + warp_m * 32 + mt * 16 + quad + ro;
            hout[(size_t)b * HQ + gbn * 32 + hloc] = O * tanhf(cn);
        }
}

__global__ void __launch_bounds__(256, 1)
decode_kernel(const float* __restrict__ X,
              float* __restrict__ h0b, float* __restrict__ h1b,
              const float* __restrict__ Wi0p, const float* __restrict__ Wh0p,
              const float* __restrict__ b0p,
              const float* __restrict__ Wi1p, const float* __restrict__ Wh1p,
              const float* __restrict__ b1p,
              const float* __restrict__ Wout, const float* __restrict__ bout,
              float* __restrict__ parts, const uint2* __restrict__ sks,
              float* __restrict__ out_s, float* __restrict__ out_l) {
    extern __shared__ float sm[];
    __shared__ float s_b0[128], s_b1[128];
    __shared__ float sv[256];
    __shared__ int   si[256];

    const int blk = blockIdx.x, tid = threadIdx.x;
    const int lid = tid & 31, wid = tid >> 5;
    const int warp_m = wid >> 2, warp_n = wid & 3;
    const int quad = lid >> 2, qi = lid & 3;

    const int gby = blk >> 5, gbn = blk & 31;                  // gates: 4 x 32
    const int lm = blk >> 5, ln = (blk >> 3) & 3, lk = blk & 7; // logits: 4 x 4 x 8

    if (tid < 128) {
        s_b0[tid] = b0p[gbn * 128 + tid];
        s_b1[tid] = b1p[gbn * 128 + tid];
    }
    __syncthreads();

    unsigned epoch = 0;
    float c0r[8], c1r[8];
#pragma unroll
    for (int i = 0; i < 8; ++i) { c0r[i] = 0.f; c1r[i] = 0.f; }
    float acc[2][4][4];

    for (int t = 0; t < LQ; ++t) {
        const int p = t & 1;
        const float* h0cur = h0b + (size_t)p * BHSZ;
        float*       h0nxt = h0b + (size_t)(p ^ 1) * BHSZ;
        const float* h1cur = h1b + (size_t)p * BHSZ;
        float*       h1nxt = h1b + (size_t)(p ^ 1) * BHSZ;

        // ===== Phase A: layer-0 gates + fused cell =====
        gemm_mma(X + (size_t)t * BHSZ, Wi0p, 32, h0cur, Wh0p, 32,
                 0, gby * 64, gbn * 128, sm, acc);
        lstm_epilogue(acc, s_b0, c0r, h0nxt, gby, gbn, warp_m, warp_n, quad, qi);
        grid_barrier(epoch);

        // ===== Phase B: layer-1 gates + fused cell =====
        gemm_mma(h0nxt, Wi1p, 32, h1cur, Wh1p, 32,
                 0, gby * 64, gbn * 128, sm, acc);
        lstm_epilogue(acc, s_b1, c1r, h1nxt, gby, gbn, warp_m, warp_n, quad, qi);
        grid_barrier(epoch);

        // ===== Phase C: logits partials (split-K 8 x 128) =====
        gemm_mma(h1nxt, Wout, 4, nullptr, nullptr, 0,
                 lk * 128, lm * 64, ln * 128, sm, acc);
        {
            float* P = parts + (size_t)lk * BQ * VQ;
#pragma unroll
            for (int mt = 0; mt < 2; ++mt)
#pragma unroll
                for (int nt = 0; nt < 4; ++nt) {
                    const float* d = acc[mt][nt];
                    const int b = lm * 64 + warp_m * 32 + mt * 16 + quad;
                    const int v = ln * 128 + warp_n * 32 + nt * 8 + qi * 2;
                    *(float2*)(P + (size_t)b * VQ + v) = make_float2(d[0], d[1]);
                    *(float2*)(P + (size_t)(b + 8) * VQ + v) = make_float2(d[2], d[3]);
                }
        }
        grid_barrier(epoch);

        // ===== Phase S: reduce + gumbel-argmax sample =====
        {
            const int r0   = blk * 2 + (tid >> 7);
            const int lane = tid & 127;
            const uint2 sk = sks[t];
            float best = -3.4e38f;
            int   bidx = 1 << 30;
            for (int v = lane; v < VQ; v += 128) {
                const int o = r0 * VQ + v;
                float lg = bout[v];
#pragma unroll
                for (int s = 0; s < 8; ++s)
                    lg += __ldcg(&parts[(size_t)s * BQ * VQ + o]);
                if (out_l) out_l[(size_t)t * BQ * VQ + o] = lg;
                uint2 rr = threefry2x32(sk.x, sk.y, 0u, (uint32_t)o);
                uint32_t bits = rr.x ^ rr.y;
                float f = __uint_as_float((bits >> 9) | 0x3f800000u) - 1.0f;
                float u = fmaxf(1.17549435e-38f, f);
                float gum = -logf(-logf(u));
                float val = lg + gum;
                if (val > best) { best = val; bidx = v; }
                else if (val == best && v < bidx) { bidx = v; }
            }
            sv[tid] = best; si[tid] = bidx;
            __syncthreads();
            for (int o = 64; o > 0; o >>= 1) {
                if ((tid & 127) < o) {
                    float v2 = sv[tid + o]; int i2 = si[tid + o];
                    if (v2 > sv[tid] || (v2 == sv[tid] && i2 < si[tid])) {
                        sv[tid] = v2; si[tid] = i2;
                    }
                }
                __syncthreads();
            }
            if ((tid & 127) == 0 && out_s) out_s[(size_t)t * BQ + r0] = (float)si[tid];
            __syncthreads();
        }
    }
}

// ---------------------------------------------------------------------------
// Host launch
// ---------------------------------------------------------------------------
extern "C" void kernel_launch(void* const* d_in, const int* in_sizes, int n_in,
                              void* d_out, int out_size) {
    const float* z    = (const float*)d_in[0];
    const float* tgt  = (const float*)d_in[1];
    const float* Wp   = (const float*)d_in[2];
    const float* bp   = (const float*)d_in[3];
    const float* Wi0  = (const float*)d_in[4];
    const float* Wh0  = (const float*)d_in[5];
    const float* bi0  = (const float*)d_in[6];
    const float* bh0  = (const float*)d_in[7];
    const float* Wi1  = (const float*)d_in[8];
    const float* Wh1  = (const float*)d_in[9];
    const float* bi1  = (const float*)d_in[10];
    const float* bh1  = (const float*)d_in[11];
    const float* Whz0 = (const float*)d_in[12];
    const float* bhz0 = (const float*)d_in[13];
    const float* Whz1 = (const float*)d_in[14];
    const float* bhz1 = (const float*)d_in[15];
    const float* Wout = (const float*)d_in[16];
    const float* bout = (const float*)d_in[17];

    float *pX, *pWpT, *ph0, *ph1, *pWi0p, *pWh0p, *pWi1p, *pWh1p, *pb0p, *pb1p, *pparts;
    int* pidx;
    uint2* psk;
    cudaGetSymbolAddress((void**)&pX, g_X);
    cudaGetSymbolAddress((void**)&pWpT, g_WpT);
    cudaGetSymbolAddress((void**)&pidx, g_idx);
    cudaGetSymbolAddress((void**)&psk, g_sk);
    cudaGetSymbolAddress((void**)&ph0, g_h0);
    cudaGetSymbolAddress((void**)&ph1, g_h1);
    cudaGetSymbolAddress((void**)&pWi0p, g_Wi0p);
    cudaGetSymbolAddress((void**)&pWh0p, g_Wh0p);
    cudaGetSymbolAddress((void**)&pWi1p, g_Wi1p);
    cudaGetSymbolAddress((void**)&pWh1p, g_Wh1p);
    cudaGetSymbolAddress((void**)&pb0p, g_b0p);
    cudaGetSymbolAddress((void**)&pb1p, g_b1p);
    cudaGetSymbolAddress((void**)&pparts, g_parts);

    const size_t LB  = (size_t)LQ * BQ;
    const size_t LBV = LB * VQ;
    float* out = (float*)d_out;
    float* out_samples = nullptr;
    float* out_logits  = nullptr;
    if ((size_t)out_size == LB + LBV) { out_samples = out; out_logits = out + LB; }
    else if ((size_t)out_size == LBV) { out_logits = out; }
    else                              { out_samples = out; }

    cudaFuncSetAttribute(decode_kernel, cudaFuncAttributeMaxDynamicSharedMemorySize,
                         DYN_SMEM);

    // ---- setup ----
    find_idx_kernel<<<(LQ * BQ) / 8, 256>>>(tgt, pidx);
    transpose_wp_kernel<<<dim3(VQ / 32, HQ / 32), dim3(32, 8)>>>(Wp, pWpT);
    key_chain_kernel<<<1, 32>>>(psk);
    init_h_kernel<<<(BQ * HQ) / 256, 256>>>(z, Whz0, bhz0, ph0);
    init_h_kernel<<<(BQ * HQ) / 256, 256>>>(z, Whz1, bhz1, ph1);
    build_x_kernel<<<(unsigned)(((size_t)LQ * BQ * HQ) / 256), 256>>>(pWpT, bp, pidx, pX);
    interleave_kernel<<<(unsigned)(((size_t)4 * G4H * HQ) / 256), 256>>>(
        Wi0, Wh0, bi0, bh0, Wi1, Wh1, bi1, bh1,
        pWi0p, pWh0p, pb0p, pWi1p, pWh1p, pb1p);

    // ---- persistent tensor-core decode ----
    decode_kernel<<<NBLK, 256, DYN_SMEM>>>(pX, ph0, ph1,
                                           pWi0p, pWh0p, pb0p,
                                           pWi1p, pWh1p, pb1p,
                                           Wout, bout, pparts, psk,
                                           out_samples, out_logits);
}